// round 13
// baseline (speedup 1.0000x reference)
#include <cuda_runtime.h>
#include <math.h>
#include <stdint.h>

#define B_ 8
#define N_ 2048
#define W_ 64
#define R_ 4
#define EPS_ 1e-8f
#define TI_ 128

typedef unsigned long long u64;

// ---------------- device scratch (zero-initialized at load) ----------------
__device__ float g_fwd [B_*R_*N_];     // REDG-accumulated fwd folds; re-zeroed by k_post
__device__ float g_bwd [B_*R_*N_];     // REDG-accumulated bwd core sums; re-zeroed by k_post
__device__ float g_cw  [B_*R_*N_];     // beta-scaled content scores
__device__ float g_ell [B_*N_];        // (1-2w)Lnn + w*p  (r-independent diag term)
__device__ float g_PSp [B_*R_*2*2];    // per-group P/S partials (2 groups)
__device__ float g_gate[B_*R_*3];
__device__ float g_P   [B_*R_];
__device__ float g_S   [B_*R_];
__device__ float g_mx  [B_*R_];
__device__ float g_inv [B_*R_];

// ---------------- f32x2 helpers ----------------
__device__ __forceinline__ u64 pk(float a, float b){
    u64 r; asm("mov.b64 %0,{%1,%2};" : "=l"(r) : "f"(a), "f"(b)); return r;
}
__device__ __forceinline__ void upk(u64 x, float& a, float& b){
    asm("mov.b64 {%0,%1},%2;" : "=f"(a), "=f"(b) : "l"(x));
}
__device__ __forceinline__ u64 add2(u64 a, u64 b){
    u64 d; asm("add.rn.f32x2 %0,%1,%2;" : "=l"(d) : "l"(a), "l"(b)); return d;
}
__device__ __forceinline__ u64 sub2(u64 a, u64 b){
    u64 d; asm("sub.rn.f32x2 %0,%1,%2;" : "=l"(d) : "l"(a), "l"(b)); return d;
}
__device__ __forceinline__ u64 mul2(u64 a, u64 b){
    u64 d; asm("mul.rn.f32x2 %0,%1,%2;" : "=l"(d) : "l"(a), "l"(b)); return d;
}
__device__ __forceinline__ u64 fma2(u64 a, u64 b, u64 c){
    u64 d; asm("fma.rn.f32x2 %0,%1,%2,%3;" : "=l"(d) : "l"(a), "l"(b), "l"(c)); return d;
}

// ================= k_fused: blocks 0-255 stream L (j-halved); 256-271 content dots ========
#define SP(sel,row,w) s_part[(((sel)*128 + (row))*16) + (w)]

__global__ void __launch_bounds__(512, 2)
k_fused(const float* __restrict__ L, const float* __restrict__ ww,
        const float* __restrict__ prw, const float* __restrict__ p,
        const float* __restrict__ mem, const float* __restrict__ controls)
{
    __shared__ u64   s_part[2*128*16];     // 32 KB fwd partials (stream path)
    __shared__ float s_a[TI_];
    __shared__ float s_pi[R_*TI_];
    __shared__ float s_diag[TI_];
    __shared__ __align__(16) float s_key[256];   // dots path
    __shared__ float s_kn[4];
    __shared__ float s_beta[4];
    __shared__ float s_prod[8][128];

    int tid = threadIdx.x, w = tid >> 5, lane = tid & 31;
    int half = lane >> 4, h = lane & 15;

    if (blockIdx.x >= 256) {
        // ===================== DOTS PATH: one block = one (b, half-of-N), 8 chunks ============
        int d = blockIdx.x - 256;        // 0..15
        int b = d >> 1, grp = d & 1;

        if (tid < 256) s_key[tid] = controls[b*272 + tid];
        if (tid >= 256 && tid < 260) {
            float x = controls[b*272 + 256 + (tid - 256)];
            s_beta[tid - 256] = 1.f + ((x > 15.f) ? x : log1pf(__expf(x)));
        }
        {   // zero P/S accumulators
            int col = tid & 127;
            for (int q = tid >> 7; q < 8; q += 4) s_prod[q][col] = 0.f;
        }
        __syncthreads();
        if (w < 4) {
            float x0 = s_key[w*64 + lane], x1 = s_key[w*64 + 32 + lane];
            float q = x0*x0 + x1*x1;
            #pragma unroll
            for (int m = 16; m; m >>= 1) q += __shfl_xor_sync(~0u, q, m);
            if (lane == 0) s_kn[w] = sqrtf(q);
        }
        __syncthreads();

        #pragma unroll 1
        for (int ck = 0; ck < 8; ++ck) {
            int n0 = (grp*8 + ck) * 128;

            if (tid < 128) {
                int n = n0 + tid;
                float pv = p [b*N_ + n];
                float wv = ww[b*N_ + n];
                #pragma unroll
                for (int r = 0; r < 4; ++r) {
                    float t = prw[(b*4+r)*N_ + n];
                    s_prod[r*2+0][tid] += pv*t;
                    s_prod[r*2+1][tid] += wv*t;
                }
            }

            #pragma unroll
            for (int it = 0; it < 4; ++it) {
                int n = n0 + w*8 + it*2 + half;
                float4 m4 = *(const float4*)(mem + ((size_t)(b*N_ + n))*W_ + h*4);
                float4 k0 = *(const float4*)(s_key + 0*64 + h*4);
                float4 k1 = *(const float4*)(s_key + 1*64 + h*4);
                float4 k2 = *(const float4*)(s_key + 2*64 + h*4);
                float4 k3 = *(const float4*)(s_key + 3*64 + h*4);
                float d0 = m4.x*k0.x + m4.y*k0.y + m4.z*k0.z + m4.w*k0.w;
                float d1 = m4.x*k1.x + m4.y*k1.y + m4.z*k1.z + m4.w*k1.w;
                float d2 = m4.x*k2.x + m4.y*k2.y + m4.z*k2.z + m4.w*k2.w;
                float d3 = m4.x*k3.x + m4.y*k3.y + m4.z*k3.z + m4.w*k3.w;
                float nr = m4.x*m4.x + m4.y*m4.y + m4.z*m4.z + m4.w*m4.w;
                u64 p01 = pk(d0, d1), p23 = pk(d2, d3);
                #pragma unroll
                for (int m = 8; m; m >>= 1) {
                    p01 = add2(p01, __shfl_xor_sync(~0u, p01, m));
                    p23 = add2(p23, __shfl_xor_sync(~0u, p23, m));
                    nr += __shfl_xor_sync(~0u, nr, m);
                }
                if (h == 0) {
                    float mns = sqrtf(nr);
                    float a0, a1, a2, a3;
                    upk(p01, a0, a1); upk(p23, a2, a3);
                    g_cw[(b*4+0)*N_ + n] = s_beta[0]*a0/(s_kn[0]*mns + EPS_);
                    g_cw[(b*4+1)*N_ + n] = s_beta[1]*a1/(s_kn[1]*mns + EPS_);
                    g_cw[(b*4+2)*N_ + n] = s_beta[2]*a2/(s_kn[2]*mns + EPS_);
                    g_cw[(b*4+3)*N_ + n] = s_beta[3]*a3/(s_kn[3]*mns + EPS_);
                }
            }
        }

        __syncthreads();
        if (w < 8) {
            float s = s_prod[w][lane] + s_prod[w][lane+32] + s_prod[w][lane+64] + s_prod[w][lane+96];
            #pragma unroll
            for (int m = 16; m; m >>= 1) s += __shfl_xor_sync(~0u, s, m);
            if (lane == 0) {
                int r = w >> 1, isS = w & 1;
                g_PSp[((b*4 + r)*2 + grp)*2 + isS] = s;
            }
        }
        return;
    }

    // ===================== STREAM PATH: block = (b, tile, jhalf); thread owns 4 j ===========
    int b = blockIdx.x >> 5;
    int rest = blockIdx.x & 31;
    int tile = rest >> 1, jh = rest & 1;
    int i0 = tile*TI_;

    if (tid < TI_) {
        s_a[tid] = 1.f - ww[b*N_ + i0 + tid];
        if (jh == 0)
            s_diag[tid] = __ldg(L + ((size_t)(b*N_ + i0 + tid))*N_ + i0 + tid);
    }
    if (tid < R_*TI_) s_pi[tid] = prw[(b*4 + (tid >> 7))*N_ + i0 + (tid & 127)];
    __syncthreads();

    int j0 = jh*1024 + w*64 + h*4;
    u64 pj[4][2];
    #pragma unroll
    for (int r = 0; r < 4; ++r) {
        float4 A = *(const float4*)(prw + (b*4+r)*N_ + j0);
        pj[r][0] = pk(A.x, A.y);  pj[r][1] = pk(A.z, A.w);
    }
    float4 wA = *(const float4*)(ww + b*N_ + j0);
    u64 wj0 = pk(wA.x, wA.y), wj1 = pk(wA.z, wA.w);

    u64 bw[4][2];
    #pragma unroll
    for (int r = 0; r < 4; ++r) { bw[r][0] = 0ull; bw[r][1] = 0ull; }

    const float* Lp = L + ((size_t)(b*N_ + i0 + half))*N_ + j0;

    float4 bA0 = __ldcs((const float4*)(Lp));
    float4 bA1 = __ldcs((const float4*)(Lp + 2*(size_t)N_));

    int g = 0;

#define STEP(BA) do {                                                        \
    int row = 2*g + half;                                                    \
    float4 A = BA;                                                           \
    int gp = g + 2; if (gp > 63) gp = 63;                                    \
    BA = __ldcs((const float4*)(Lp + (size_t)(2*gp)*N_));                    \
    u64 l0 = pk(A.x,A.y), l1 = pk(A.z,A.w);                                  \
    float a = s_a[row];                                                      \
    u64 av = pk(a, a);                                                       \
    u64 c0 = mul2(sub2(av, wj0), l0);                                        \
    u64 c1 = mul2(sub2(av, wj1), l1);                                        \
    float f[4];                                                              \
    _Pragma("unroll")                                                        \
    for (int r = 0; r < 4; ++r) {                                            \
        u64 t = mul2(c0, pj[r][0]);                                          \
        t = fma2(c1, pj[r][1], t);                                           \
        float x, y; upk(t, x, y); f[r] = x + y;                              \
        float pi = s_pi[r*128 + row];                                        \
        u64 pr = pk(pi, pi);                                                 \
        bw[r][0] = fma2(c0, pr, bw[r][0]);                                   \
        bw[r][1] = fma2(c1, pr, bw[r][1]);                                   \
    }                                                                        \
    u64 f01 = pk(f[0], f[1]), f23 = pk(f[2], f[3]);                          \
    _Pragma("unroll")                                                        \
    for (int m = 8; m; m >>= 1) {                                            \
        f01 = add2(f01, __shfl_xor_sync(~0u, f01, m));                       \
        f23 = add2(f23, __shfl_xor_sync(~0u, f23, m));                       \
    }                                                                        \
    if (h == 0) { SP(0, row, w) = f01; SP(1, row, w) = f23; }                \
    ++g;                                                                     \
} while (0)

    #pragma unroll 1
    for (int gb = 0; gb < 32; ++gb) {   // 64 row-pairs
        STEP(bA0);
        STEP(bA1);
    }
#undef STEP

    // bwd: combine halves, REDG-accumulate into g_bwd
    #pragma unroll
    for (int r = 0; r < 4; ++r) {
        bw[r][0] = add2(bw[r][0], __shfl_xor_sync(~0u, bw[r][0], 16));
        bw[r][1] = add2(bw[r][1], __shfl_xor_sync(~0u, bw[r][1], 16));
    }
    if (half == 0) {
        #pragma unroll
        for (int r = 0; r < 4; ++r) {
            float* dst = g_bwd + (size_t)(b*4 + r)*N_ + j0;
            float x0, x1, x2, x3;
            upk(bw[r][0], x0, x1); upk(bw[r][1], x2, x3);
            atomicAdd(dst + 0, x0); atomicAdd(dst + 1, x1);
            atomicAdd(dst + 2, x2); atomicAdd(dst + 3, x3);
        }
    }
    __syncthreads();

    // fwd fold (partial over this j-half) -> REDG into g_fwd; emit ell (jh==0, r==0)
    {
        int row = tid >> 2, r = tid & 3;
        int br = b*4 + r;
        int n = i0 + row;
        const float* sp = (const float*)&SP(r >> 1, row, 0);
        float sfold = 0.f;
        #pragma unroll
        for (int w2 = 0; w2 < 16; ++w2) sfold += sp[w2*2 + (r & 1)];
        atomicAdd(&g_fwd[br*N_ + n], sfold);
        if (r == 0 && jh == 0) {
            float wn = 1.f - s_a[row];
            float pn = p[b*N_ + n];
            g_ell[b*N_ + n] = (1.f - 2.f*wn)*s_diag[row] + wn*pn;
        }
    }
}

// ================= k_red: P/S sums, gates, softmax mx & 1/Z, zero out. 32 blocks =================
__global__ void __launch_bounds__(256)
k_red(const float* __restrict__ controls, float* __restrict__ out)
{
    int br = blockIdx.x, b = br >> 2, r = br & 3;
    int tid = threadIdx.x, warp = tid >> 5, lane = tid & 31;
    __shared__ float s_r[8];
    __shared__ float s_bc;

    if (tid < 64) out[br*64 + tid] = 0.f;

    float v[8]; float mx = -1e30f;
    #pragma unroll
    for (int k = 0; k < 8; ++k) { v[k] = g_cw[br*N_ + tid + k*256]; mx = fmaxf(mx, v[k]); }
    #pragma unroll
    for (int m = 16; m; m >>= 1) mx = fmaxf(mx, __shfl_xor_sync(~0u, mx, m));
    if (lane == 0) s_r[warp] = mx;
    __syncthreads();
    if (tid == 0) { float m2 = s_r[0]; for (int i = 1; i < 8; ++i) m2 = fmaxf(m2, s_r[i]); s_bc = m2; }
    __syncthreads();
    mx = s_bc;
    float s = 0.f;
    #pragma unroll
    for (int k = 0; k < 8; ++k) s += __expf(v[k] - mx);
    #pragma unroll
    for (int m = 16; m; m >>= 1) s += __shfl_xor_sync(~0u, s, m);
    __syncthreads();
    if (lane == 0) s_r[warp] = s;
    __syncthreads();
    if (tid == 0) {
        float t = 0.f;
        for (int i = 0; i < 8; ++i) t += s_r[i];
        g_mx[br] = mx; g_inv[br] = 1.f/t;

        float P = g_PSp[(br*2+0)*2+0] + g_PSp[(br*2+1)*2+0];
        float S = g_PSp[(br*2+0)*2+1] + g_PSp[(br*2+1)*2+1];
        g_P[br] = P; g_S[br] = S;
        float e0 = controls[b*272 + 260 + r*3 + 0];
        float e1 = controls[b*272 + 260 + r*3 + 1];
        float e2 = controls[b*272 + 260 + r*3 + 2];
        float mm = fmaxf(e0, fmaxf(e1, e2));
        float x0 = __expf(e0-mm), x1 = __expf(e1-mm), x2 = __expf(e2-mm);
        float inv = 1.f/(x0+x1+x2);
        g_gate[br*3+0] = x0*inv; g_gate[br*3+1] = x1*inv; g_gate[br*3+2] = x2*inv;
    }
}

// ================= k_post: corrections + exp + rw + read vector; re-zeroes g_fwd/g_bwd =====
__global__ void __launch_bounds__(256, 1)
k_post(const float* __restrict__ mem, const float* __restrict__ ww,
       const float* __restrict__ p, const float* __restrict__ prw,
       float* __restrict__ out)
{
    int b = blockIdx.x >> 5, c = blockIdx.x & 31;
    int n0 = c*64;
    int tid = threadIdx.x, warp = tid >> 5, lane = tid & 31;
    __shared__ float s_rw[4][64];
    __shared__ float s_g[12];
    __shared__ float s_mx[4], s_inv[4], s_P[4], s_S[4];
    __shared__ float s_acc[8][4][64];

    if (tid < 12) s_g[tid] = g_gate[b*12 + tid];
    if (tid >= 16 && tid < 20) s_mx [tid-16] = g_mx [b*4 + tid-16];
    if (tid >= 20 && tid < 24) s_inv[tid-20] = g_inv[b*4 + tid-20];
    if (tid >= 24 && tid < 28) s_P  [tid-24] = g_P  [b*4 + tid-24];
    if (tid >= 28 && tid < 32) s_S  [tid-28] = g_S  [b*4 + tid-28];
    __syncthreads();

    {
        int r = tid >> 6, nl = tid & 63;
        int br = b*4 + r, n = n0 + nl;
        float wn  = ww[b*N_ + n];
        float pn  = p [b*N_ + n];
        float ell = g_ell[b*N_ + n];
        float prn = prw[br*N_ + n];
        float fwd = g_fwd[br*N_ + n] + wn*s_P[r] - ell*prn;
        float bwd = g_bwd[br*N_ + n] + pn*s_S[r] - ell*prn;
        float cwv = __expf(g_cw[br*N_ + n] - s_mx[r]) * s_inv[r];
        s_rw[r][nl] = s_g[r*3+0]*fwd + s_g[r*3+1]*bwd + s_g[r*3+2]*cwv;
        g_bwd[br*N_ + n] = 0.f;   // restore state for next graph replay
        g_fwd[br*N_ + n] = 0.f;
    }
    __syncthreads();

    float2 acc[4];
    #pragma unroll
    for (int r = 0; r < 4; ++r) { acc[r].x = 0.f; acc[r].y = 0.f; }
    #pragma unroll
    for (int k = 0; k < 8; ++k) {
        int nl = warp*8 + k;
        float2 m = *(const float2*)(mem + ((size_t)(b*N_ + n0 + nl))*W_ + lane*2);
        #pragma unroll
        for (int r = 0; r < 4; ++r) {
            float rv = s_rw[r][nl];
            acc[r].x += m.x*rv;
            acc[r].y += m.y*rv;
        }
    }
    #pragma unroll
    for (int r = 0; r < 4; ++r) {
        s_acc[warp][r][lane*2]   = acc[r].x;
        s_acc[warp][r][lane*2+1] = acc[r].y;
    }
    __syncthreads();
    {
        int r = tid >> 6, wd = tid & 63;
        float s = 0.f;
        #pragma unroll
        for (int k = 0; k < 8; ++k) s += s_acc[k][r][wd];
        atomicAdd(&out[(b*4 + r)*64 + wd], s);
    }
}

// ================= launcher =================
extern "C" void kernel_launch(void* const* d_in, const int* in_sizes, int n_in,
                              void* d_out, int out_size)
{
    const float* mem      = (const float*)d_in[0];
    const float* controls = (const float*)d_in[1];
    const float* ww       = (const float*)d_in[2];
    const float* L        = (const float*)d_in[3];
    const float* p        = (const float*)d_in[4];
    const float* prw      = (const float*)d_in[5];
    float* out = (float*)d_out;

    k_fused<<<272, 512>>>(L, ww, prw, p, mem, controls);
    k_red  <<<B_*R_, 256>>>(controls, out);
    k_post <<<B_*32, 256>>>(mem, ww, p, prw, out);
}

// round 15
// speedup vs baseline: 1.2955x; 1.2955x over previous
#include <cuda_runtime.h>
#include <math.h>
#include <stdint.h>

#define B_ 8
#define N_ 2048
#define W_ 64
#define R_ 4
#define EPS_ 1e-8f
#define TI_ 128

typedef unsigned long long u64;

// ---------------- device scratch (zero-initialized at load) ----------------
__device__ float g_fwd [B_*R_*N_];     // raw fwd fold (corrections in k_post)
__device__ float g_bwd [B_*R_*N_];     // REDG-accumulated bwd core sums; re-zeroed by k_post
__device__ float g_cw  [B_*R_*N_];     // beta-scaled content scores
__device__ float g_ell [B_*N_];        // (1-2w)Lnn + w*p  (r-independent diag term)
__device__ float g_PSp [B_*R_*2*2];    // per-group P/S partials (2 groups)
__device__ float g_sm  [B_*R_*2*2];    // per-group softmax partials: (max, Z)
__device__ float g_gate[B_*R_*3];

// ---------------- f32x2 helpers ----------------
__device__ __forceinline__ u64 pk(float a, float b){
    u64 r; asm("mov.b64 %0,{%1,%2};" : "=l"(r) : "f"(a), "f"(b)); return r;
}
__device__ __forceinline__ void upk(u64 x, float& a, float& b){
    asm("mov.b64 {%0,%1},%2;" : "=f"(a), "=f"(b) : "l"(x));
}
__device__ __forceinline__ u64 add2(u64 a, u64 b){
    u64 d; asm("add.rn.f32x2 %0,%1,%2;" : "=l"(d) : "l"(a), "l"(b)); return d;
}
__device__ __forceinline__ u64 sub2(u64 a, u64 b){
    u64 d; asm("sub.rn.f32x2 %0,%1,%2;" : "=l"(d) : "l"(a), "l"(b)); return d;
}
__device__ __forceinline__ u64 mul2(u64 a, u64 b){
    u64 d; asm("mul.rn.f32x2 %0,%1,%2;" : "=l"(d) : "l"(a), "l"(b)); return d;
}
__device__ __forceinline__ u64 fma2(u64 a, u64 b, u64 c){
    u64 d; asm("fma.rn.f32x2 %0,%1,%2,%3;" : "=l"(d) : "l"(a), "l"(b), "l"(c)); return d;
}

// ================= k_fused: blocks 0-127 stream L; blocks 128-143 content dots =============
#define SP(sel,row,w) s_part[(((sel)*128 + (row))*16) + (w)]

__global__ void __launch_bounds__(512, 1)
k_fused(const float* __restrict__ L, const float* __restrict__ ww,
        const float* __restrict__ prw, const float* __restrict__ p,
        const float* __restrict__ mem, const float* __restrict__ controls,
        float* __restrict__ out)
{
    __shared__ u64   s_part[2*128*16];     // 32 KB fwd partials (stream path)
    __shared__ float s_a[TI_];
    __shared__ float s_pi[R_*TI_];
    __shared__ float s_diag[TI_];
    __shared__ __align__(16) float s_key[256];   // dots path
    __shared__ float s_kn[4];
    __shared__ float s_beta[4];
    __shared__ float s_prod[8][128];
    __shared__ float s_sm[4][32];          // per-(warp,half) online-softmax max
    __shared__ float s_sz[4][32];          // per-(warp,half) online-softmax Z

    int tid = threadIdx.x, w = tid >> 5, lane = tid & 31;
    int half = lane >> 4, h = lane & 15;

    if (blockIdx.x >= 128) {
        // ===================== DOTS PATH: one block = one (b, half-of-N), 8 chunks ============
        int d = blockIdx.x - 128;        // 0..15
        int b = d >> 1, grp = d & 1;

        if (tid < 256) s_key[tid] = controls[b*272 + tid];
        if (tid >= 256 && tid < 260) {
            float x = controls[b*272 + 256 + (tid - 256)];
            s_beta[tid - 256] = 1.f + ((x > 15.f) ? x : log1pf(__expf(x)));
        }
        // gates (grp 0 only); out zeroing (grp 0 only)
        if (grp == 0 && tid >= 288 && tid < 292) {
            int r = tid - 288;
            float e0 = controls[b*272 + 260 + r*3 + 0];
            float e1 = controls[b*272 + 260 + r*3 + 1];
            float e2 = controls[b*272 + 260 + r*3 + 2];
            float mm = fmaxf(e0, fmaxf(e1, e2));
            float x0 = __expf(e0-mm), x1 = __expf(e1-mm), x2 = __expf(e2-mm);
            float inv = 1.f/(x0+x1+x2);
            g_gate[(b*4+r)*3+0] = x0*inv;
            g_gate[(b*4+r)*3+1] = x1*inv;
            g_gate[(b*4+r)*3+2] = x2*inv;
        }
        if (grp == 0 && tid < 256) out[b*256 + tid] = 0.f;
        {   // zero P/S accumulators
            int col = tid & 127;
            for (int q = tid >> 7; q < 8; q += 4) s_prod[q][col] = 0.f;
        }
        __syncthreads();
        if (w < 4) {
            float x0 = s_key[w*64 + lane], x1 = s_key[w*64 + 32 + lane];
            float q = x0*x0 + x1*x1;
            #pragma unroll
            for (int m = 16; m; m >>= 1) q += __shfl_xor_sync(~0u, q, m);
            if (lane == 0) s_kn[w] = sqrtf(q);
        }
        __syncthreads();

        // online softmax state (meaningful at h==0 lanes only)
        float om[4], oz[4];
        #pragma unroll
        for (int r = 0; r < 4; ++r) { om[r] = -1e30f; oz[r] = 0.f; }

        #pragma unroll 1
        for (int ck = 0; ck < 8; ++ck) {
            int n0 = (grp*8 + ck) * 128;

            if (tid < 128) {
                int n = n0 + tid;
                float pv = p [b*N_ + n];
                float wv = ww[b*N_ + n];
                #pragma unroll
                for (int r = 0; r < 4; ++r) {
                    float t = prw[(b*4+r)*N_ + n];
                    s_prod[r*2+0][tid] += pv*t;
                    s_prod[r*2+1][tid] += wv*t;
                }
            }

            #pragma unroll
            for (int it = 0; it < 4; ++it) {
                int n = n0 + w*8 + it*2 + half;
                float4 m4 = *(const float4*)(mem + ((size_t)(b*N_ + n))*W_ + h*4);
                float4 k0 = *(const float4*)(s_key + 0*64 + h*4);
                float4 k1 = *(const float4*)(s_key + 1*64 + h*4);
                float4 k2 = *(const float4*)(s_key + 2*64 + h*4);
                float4 k3 = *(const float4*)(s_key + 3*64 + h*4);
                float d0 = m4.x*k0.x + m4.y*k0.y + m4.z*k0.z + m4.w*k0.w;
                float d1 = m4.x*k1.x + m4.y*k1.y + m4.z*k1.z + m4.w*k1.w;
                float d2 = m4.x*k2.x + m4.y*k2.y + m4.z*k2.z + m4.w*k2.w;
                float d3 = m4.x*k3.x + m4.y*k3.y + m4.z*k3.z + m4.w*k3.w;
                float nr = m4.x*m4.x + m4.y*m4.y + m4.z*m4.z + m4.w*m4.w;
                u64 p01 = pk(d0, d1), p23 = pk(d2, d3);
                #pragma unroll
                for (int m = 8; m; m >>= 1) {
                    p01 = add2(p01, __shfl_xor_sync(~0u, p01, m));
                    p23 = add2(p23, __shfl_xor_sync(~0u, p23, m));
                    nr += __shfl_xor_sync(~0u, nr, m);
                }
                if (h == 0) {
                    float mns = sqrtf(nr);
                    float sc[4];
                    upk(p01, sc[0], sc[1]); upk(p23, sc[2], sc[3]);
                    #pragma unroll
                    for (int r = 0; r < 4; ++r) {
                        float s = s_beta[r]*sc[r]/(s_kn[r]*mns + EPS_);
                        g_cw[(b*4+r)*N_ + n] = s;
                        float nm = fmaxf(om[r], s);
                        oz[r] = oz[r]*__expf(om[r]-nm) + __expf(s-nm);
                        om[r] = nm;
                    }
                }
            }
        }

        // slot write + merge
        if (h == 0) {
            int slot = w*2 + half;
            #pragma unroll
            for (int r = 0; r < 4; ++r) { s_sm[r][slot] = om[r]; s_sz[r][slot] = oz[r]; }
        }
        __syncthreads();
        if (tid < 128) {
            int r = w;                     // warp 0..3 handles r
            float m = s_sm[r][lane], z = s_sz[r][lane];
            #pragma unroll
            for (int off = 16; off; off >>= 1) {
                float m2 = __shfl_xor_sync(~0u, m, off);
                float z2 = __shfl_xor_sync(~0u, z, off);
                float nm = fmaxf(m, m2);
                z = z*__expf(m-nm) + z2*__expf(m2-nm);
                m = nm;
            }
            if (lane == 0) {
                g_sm[((b*4+r)*2 + grp)*2 + 0] = m;
                g_sm[((b*4+r)*2 + grp)*2 + 1] = z;
            }
        }
        __syncthreads();
        if (w < 8) {
            float s = s_prod[w][lane] + s_prod[w][lane+32] + s_prod[w][lane+64] + s_prod[w][lane+96];
            #pragma unroll
            for (int m = 16; m; m >>= 1) s += __shfl_xor_sync(~0u, s, m);
            if (lane == 0) {
                int r = w >> 1, isS = w & 1;
                g_PSp[((b*4 + r)*2 + grp)*2 + isS] = s;
            }
        }
        return;
    }

    // ===================== STREAM PATH (R12-exact; epilogue emits raw fwd + ell) =============
    int b = blockIdx.x >> 4, tile = blockIdx.x & 15, i0 = tile*TI_;

    if (tid < TI_) {
        s_a[tid]    = 1.f - ww[b*N_ + i0 + tid];
        s_diag[tid] = __ldg(L + ((size_t)(b*N_ + i0 + tid))*N_ + i0 + tid);
    }
    if (tid < R_*TI_) s_pi[tid] = prw[(b*4 + (tid >> 7))*N_ + i0 + (tid & 127)];
    __syncthreads();

    int jA = w*128 + h*4, jB = jA + 64;
    u64 pj[4][4];
    #pragma unroll
    for (int r = 0; r < 4; ++r) {
        float4 A  = *(const float4*)(prw + (b*4+r)*N_ + jA);
        float4 Bv = *(const float4*)(prw + (b*4+r)*N_ + jB);
        pj[r][0] = pk(A.x, A.y);  pj[r][1] = pk(A.z, A.w);
        pj[r][2] = pk(Bv.x, Bv.y); pj[r][3] = pk(Bv.z, Bv.w);
    }
    float4 wA = *(const float4*)(ww + b*N_ + jA);
    float4 wB = *(const float4*)(ww + b*N_ + jB);
    u64 wj[4] = { pk(wA.x,wA.y), pk(wA.z,wA.w), pk(wB.x,wB.y), pk(wB.z,wB.w) };

    u64 bw[4][4];
    #pragma unroll
    for (int r = 0; r < 4; ++r)
        #pragma unroll
        for (int k = 0; k < 4; ++k) bw[r][k] = 0ull;

    const float* Lp = L + ((size_t)(b*N_ + i0 + half))*N_ + jA;

    float4 bA0 = __ldcs((const float4*)(Lp));
    float4 bB0 = __ldcs((const float4*)(Lp + 64));
    float4 bA1 = __ldcs((const float4*)(Lp + 2*(size_t)N_));
    float4 bB1 = __ldcs((const float4*)(Lp + 2*(size_t)N_ + 64));
    float4 bA2 = __ldcs((const float4*)(Lp + 4*(size_t)N_));
    float4 bB2 = __ldcs((const float4*)(Lp + 4*(size_t)N_ + 64));

    int g = 0;

#define STEP(BA,BB) do {                                                     \
    int row = 2*g + half;                                                    \
    float4 A = BA, Bv = BB;                                                  \
    int gp = g + 3; if (gp > 63) gp = 63;                                    \
    const float* np = Lp + (size_t)(2*gp)*N_;                                \
    BA = __ldcs((const float4*)np);                                          \
    BB = __ldcs((const float4*)(np + 64));                                   \
    u64 l0 = pk(A.x,A.y), l1 = pk(A.z,A.w), l2 = pk(Bv.x,Bv.y), l3 = pk(Bv.z,Bv.w); \
    float a = s_a[row];                                                      \
    u64 av = pk(a, a);                                                       \
    u64 c0 = mul2(sub2(av, wj[0]), l0);                                      \
    u64 c1 = mul2(sub2(av, wj[1]), l1);                                      \
    u64 c2 = mul2(sub2(av, wj[2]), l2);                                      \
    u64 c3 = mul2(sub2(av, wj[3]), l3);                                      \
    float f[4];                                                              \
    _Pragma("unroll")                                                        \
    for (int r = 0; r < 4; ++r) {                                            \
        u64 t = mul2(c0, pj[r][0]);                                          \
        t = fma2(c1, pj[r][1], t);                                           \
        t = fma2(c2, pj[r][2], t);                                           \
        t = fma2(c3, pj[r][3], t);                                           \
        float x, y; upk(t, x, y); f[r] = x + y;                              \
        float pi = s_pi[r*128 + row];                                        \
        u64 pr = pk(pi, pi);                                                 \
        bw[r][0] = fma2(c0, pr, bw[r][0]);                                   \
        bw[r][1] = fma2(c1, pr, bw[r][1]);                                   \
        bw[r][2] = fma2(c2, pr, bw[r][2]);                                   \
        bw[r][3] = fma2(c3, pr, bw[r][3]);                                   \
    }                                                                        \
    u64 f01 = pk(f[0], f[1]), f23 = pk(f[2], f[3]);                          \
    _Pragma("unroll")                                                        \
    for (int m = 8; m; m >>= 1) {                                            \
        f01 = add2(f01, __shfl_xor_sync(~0u, f01, m));                       \
        f23 = add2(f23, __shfl_xor_sync(~0u, f23, m));                       \
    }                                                                        \
    if (h == 0) { SP(0, row, w) = f01; SP(1, row, w) = f23; }                \
    ++g;                                                                     \
} while (0)

    #pragma unroll 1
    for (int gb = 0; gb < 21; ++gb) {   // 63 row-pairs
        STEP(bA0, bB0);
        STEP(bA1, bB1);
        STEP(bA2, bB2);
    }
    STEP(bA0, bB0);                     // g = 63 (prefetch clamps, redundant)
#undef STEP

    // bwd: combine halves, REDG-accumulate into g_bwd
    #pragma unroll
    for (int r = 0; r < 4; ++r)
        #pragma unroll
        for (int k = 0; k < 4; ++k)
            bw[r][k] = add2(bw[r][k], __shfl_xor_sync(~0u, bw[r][k], 16));
    if (half == 0) {
        #pragma unroll
        for (int r = 0; r < 4; ++r) {
            float* dst = g_bwd + (size_t)(b*4 + r)*N_;
            float x0, x1, x2, x3, x4, x5, x6, x7;
            upk(bw[r][0], x0, x1); upk(bw[r][1], x2, x3);
            upk(bw[r][2], x4, x5); upk(bw[r][3], x6, x7);
            atomicAdd(dst + jA + 0, x0); atomicAdd(dst + jA + 1, x1);
            atomicAdd(dst + jA + 2, x2); atomicAdd(dst + jA + 3, x3);
            atomicAdd(dst + jB + 0, x4); atomicAdd(dst + jB + 1, x5);
            atomicAdd(dst + jB + 2, x6); atomicAdd(dst + jB + 3, x7);
        }
    }
    __syncthreads();

    // fwd fold (raw) + emit r-independent diag term
    {
        int row = tid >> 2, r = tid & 3;
        int br = b*4 + r;
        int n = i0 + row;
        const float* sp = (const float*)&SP(r >> 1, row, 0);
        float sfold = 0.f;
        #pragma unroll
        for (int w2 = 0; w2 < 16; ++w2) sfold += sp[w2*2 + (r & 1)];
        g_fwd[br*N_ + n] = sfold;
        if (r == 0) {
            float wn = 1.f - s_a[row];
            float pn = p[b*N_ + n];
            g_ell[b*N_ + n] = (1.f - 2.f*wn)*s_diag[row] + wn*pn;
        }
    }
}

// ================= k_post: combine partials + corrections + exp + rw + read vector ========
__global__ void __launch_bounds__(256, 1)
k_post(const float* __restrict__ mem, const float* __restrict__ ww,
       const float* __restrict__ p, const float* __restrict__ prw,
       float* __restrict__ out)
{
    int b = blockIdx.x >> 5, c = blockIdx.x & 31;
    int n0 = c*64;
    int tid = threadIdx.x, warp = tid >> 5, lane = tid & 31;
    __shared__ float s_rw[4][64];
    __shared__ float s_g[12];
    __shared__ float s_mx[4], s_inv[4], s_P[4], s_S[4];
    __shared__ float s_acc[8][4][64];

    if (tid < 12) s_g[tid] = g_gate[b*12 + tid];
    if (tid >= 16 && tid < 20) {
        int r = tid - 16, br = b*4 + r;
        float m0 = g_sm[(br*2+0)*2+0], z0 = g_sm[(br*2+0)*2+1];
        float m1 = g_sm[(br*2+1)*2+0], z1 = g_sm[(br*2+1)*2+1];
        float mx = fmaxf(m0, m1);
        float Z = z0*__expf(m0-mx) + z1*__expf(m1-mx);
        s_mx[r] = mx; s_inv[r] = 1.f/Z;
        s_P[r] = g_PSp[(br*2+0)*2+0] + g_PSp[(br*2+1)*2+0];
        s_S[r] = g_PSp[(br*2+0)*2+1] + g_PSp[(br*2+1)*2+1];
    }
    __syncthreads();

    {
        int r = tid >> 6, nl = tid & 63;
        int br = b*4 + r, n = n0 + nl;
        float wn  = ww[b*N_ + n];
        float pn  = p [b*N_ + n];
        float ell = g_ell[b*N_ + n];
        float prn = prw[br*N_ + n];
        float fwd = g_fwd[br*N_ + n] + wn*s_P[r] - ell*prn;
        float bwd = g_bwd[br*N_ + n] + pn*s_S[r] - ell*prn;
        float cwv = __expf(g_cw[br*N_ + n] - s_mx[r]) * s_inv[r];
        s_rw[r][nl] = s_g[r*3+0]*fwd + s_g[r*3+1]*bwd + s_g[r*3+2]*cwv;
        g_bwd[br*N_ + n] = 0.f;   // restore state for next graph replay
    }
    __syncthreads();

    float2 acc[4];
    #pragma unroll
    for (int r = 0; r < 4; ++r) { acc[r].x = 0.f; acc[r].y = 0.f; }
    #pragma unroll
    for (int k = 0; k < 8; ++k) {
        int nl = warp*8 + k;
        float2 m = *(const float2*)(mem + ((size_t)(b*N_ + n0 + nl))*W_ + lane*2);
        #pragma unroll
        for (int r = 0; r < 4; ++r) {
            float rv = s_rw[r][nl];
            acc[r].x += m.x*rv;
            acc[r].y += m.y*rv;
        }
    }
    #pragma unroll
    for (int r = 0; r < 4; ++r) {
        s_acc[warp][r][lane*2]   = acc[r].x;
        s_acc[warp][r][lane*2+1] = acc[r].y;
    }
    __syncthreads();
    {
        int r = tid >> 6, wd = tid & 63;
        float s = 0.f;
        #pragma unroll
        for (int k = 0; k < 8; ++k) s += s_acc[k][r][wd];
        atomicAdd(&out[(b*4 + r)*64 + wd], s);
    }
}

// ================= launcher =================
extern "C" void kernel_launch(void* const* d_in, const int* in_sizes, int n_in,
                              void* d_out, int out_size)
{
    const float* mem      = (const float*)d_in[0];
    const float* controls = (const float*)d_in[1];
    const float* ww       = (const float*)d_in[2];
    const float* L        = (const float*)d_in[3];
    const float* p        = (const float*)d_in[4];
    const float* prw      = (const float*)d_in[5];
    float* out = (float*)d_out;

    k_fused<<<144, 512>>>(L, ww, prw, p, mem, controls, out);
    k_post <<<B_*32, 256>>>(mem, ww, p, prw, out);
}